// round 2
// baseline (speedup 1.0000x reference)
#include <cuda_runtime.h>

// ---------------- problem constants ----------------
constexpr int B   = 128;
constexpr int N   = 4096;
constexpr int OUT = 64;
constexpr int F1 = 64, F2 = 128, F3 = 256;

constexpr int WARPS = 8;           // warps per block
constexpr int WPTS  = 8;           // points per warp per group
constexpr int GROUP = WARPS * WPTS;        // 64 points per block-iteration
constexpr int PTS_PER_BLOCK = 256;         // 4 groups per block
constexpr int BLOCKS_X = N / PTS_PER_BLOCK; // 16

// global max-pool accumulator (relu => values >= 0, init to 0 is exact)
__device__ float g_agg[B * F3];

// ---------------- shared memory layout ----------------
struct Smem {
    float w3[F2][F3];          // 131072 B
    float w2[F1][F2];          //  32768 B
    float h2[WARPS][WPTS][F2]; //  32768 B
    float h1[WARPS][WPTS][F1]; //  16384 B  (reused as [WARPS][F3] reduce buf)
    float w1[2][F1];           //    512 B
    float b1[F1];              //    256 B
    float b2[F2];              //    512 B
    float b3[F3];              //   1024 B
};                              // total 215296 B

// ---------------- packed f32x2 helpers ----------------
__device__ __forceinline__ unsigned long long ldb64(const float* p) {
    return *reinterpret_cast<const unsigned long long*>(p);
}
__device__ __forceinline__ unsigned long long pack2(float h) {
    unsigned long long d;
    asm("mov.b64 %0, {%1, %1};" : "=l"(d) : "f"(h));
    return d;
}
__device__ __forceinline__ void fma2(unsigned long long& d,
                                     unsigned long long a,
                                     unsigned long long b) {
    asm("fma.rn.f32x2 %0, %1, %2, %0;" : "+l"(d) : "l"(a), "l"(b));
}
__device__ __forceinline__ float lo32(unsigned long long v) {
    return __uint_as_float((unsigned)(v & 0xFFFFFFFFull));
}
__device__ __forceinline__ float hi32(unsigned long long v) {
    return __uint_as_float((unsigned)(v >> 32));
}

// ---------------- kernels ----------------
__global__ void init_agg_kernel() {
    int i = blockIdx.x * blockDim.x + threadIdx.x;
    if (i < B * F3) g_agg[i] = 0.0f;
}

__global__ void __launch_bounds__(256, 1)
phi_kernel(const float* __restrict__ points, const int* __restrict__ lengths,
           const float* __restrict__ w1, const float* __restrict__ b1,
           const float* __restrict__ w2, const float* __restrict__ b2,
           const float* __restrict__ w3, const float* __restrict__ b3)
{
    const int b   = blockIdx.y;
    const int len = lengths[b];
    const int base = blockIdx.x * PTS_PER_BLOCK;
    if (base >= len) return;   // block-uniform early exit (before any sync)

    extern __shared__ char raw[];
    Smem& s = *reinterpret_cast<Smem*>(raw);

    const int tid  = threadIdx.x;
    const int w    = tid >> 5;
    const int lane = tid & 31;

    // ---- stage weights/biases into SMEM (vectorized) ----
    {
        const float4* g3 = reinterpret_cast<const float4*>(w3);
        float4*       s3 = reinterpret_cast<float4*>(&s.w3[0][0]);
        for (int i = tid; i < F2 * F3 / 4; i += 256) s3[i] = g3[i];
        const float4* g2 = reinterpret_cast<const float4*>(w2);
        float4*       s2 = reinterpret_cast<float4*>(&s.w2[0][0]);
        for (int i = tid; i < F1 * F2 / 4; i += 256) s2[i] = g2[i];
        if (tid < 2 * F1) (&s.w1[0][0])[tid] = w1[tid];
        if (tid < F1)  s.b1[tid] = b1[tid];
        if (tid < F2)  s.b2[tid] = b2[tid];
        s.b3[tid] = b3[tid];   // F3 == 256 == blockDim
    }
    __syncthreads();

    // running max per lane: m[2*j+idx] <-> feature f = 2*lane + 64*j + idx
    float m[8];
#pragma unroll
    for (int j = 0; j < 8; j++) m[j] = 0.0f;

    // preload bias pairs for h2 / h3 (feature pair f = 2*(lane + 32*j))
    const unsigned long long bias2_0 = ldb64(&s.b2[2 * lane]);
    const unsigned long long bias2_1 = ldb64(&s.b2[2 * lane + 64]);
    unsigned long long bias3[4];
#pragma unroll
    for (int j = 0; j < 4; j++) bias3[j] = ldb64(&s.b3[2 * lane + 64 * j]);

    for (int g0 = base; g0 < base + PTS_PER_BLOCK; g0 += GROUP) {
        const int gw = g0 + w * WPTS;       // first point of this warp's group
        if (gw >= len) continue;            // warp-uniform

        // ---- load 8 points, broadcast via shuffle ----
        float x = 0.0f, y = 0.0f;
        if (lane < WPTS) {
            int n = gw + lane;
            if (n < len) {
                const float* pp = points + ((long long)b * N + n) * 2;
                x = pp[0];
                y = pp[1];
            }
        }
        float xs[WPTS], ys[WPTS];
#pragma unroll
        for (int p = 0; p < WPTS; p++) {
            xs[p] = __shfl_sync(0xFFFFFFFFu, x, p);
            ys[p] = __shfl_sync(0xFFFFFFFFu, y, p);
        }

        // ---- layer 1: 2 -> 64 (each lane: feats lane, lane+32) ----
#pragma unroll
        for (int p = 0; p < WPTS; p++) {
            float v0 = fmaf(xs[p], s.w1[0][lane],
                       fmaf(ys[p], s.w1[1][lane], s.b1[lane]));
            float v1 = fmaf(xs[p], s.w1[0][lane + 32],
                       fmaf(ys[p], s.w1[1][lane + 32], s.b1[lane + 32]));
            s.h1[w][p][lane]      = fmaxf(v0, 0.0f);
            s.h1[w][p][lane + 32] = fmaxf(v1, 0.0f);
        }
        __syncwarp();

        // ---- layer 2: 64 -> 128, register tile 2 f32x2-pairs x 8 points ----
        {
            unsigned long long acc[WPTS][2];
#pragma unroll
            for (int p = 0; p < WPTS; p++) { acc[p][0] = bias2_0; acc[p][1] = bias2_1; }

#pragma unroll 2
            for (int k = 0; k < F1; k++) {
                const unsigned long long wv0 = ldb64(&s.w2[k][2 * lane]);
                const unsigned long long wv1 = ldb64(&s.w2[k][2 * lane + 64]);
#pragma unroll
                for (int p = 0; p < WPTS; p++) {
                    const unsigned long long hh = pack2(s.h1[w][p][k]);
                    fma2(acc[p][0], wv0, hh);
                    fma2(acc[p][1], wv1, hh);
                }
            }
#pragma unroll
            for (int p = 0; p < WPTS; p++) {
                s.h2[w][p][2 * lane]      = fmaxf(lo32(acc[p][0]), 0.0f);
                s.h2[w][p][2 * lane + 1]  = fmaxf(hi32(acc[p][0]), 0.0f);
                s.h2[w][p][2 * lane + 64] = fmaxf(lo32(acc[p][1]), 0.0f);
                s.h2[w][p][2 * lane + 65] = fmaxf(hi32(acc[p][1]), 0.0f);
            }
        }
        __syncwarp();

        // ---- layer 3: 128 -> 256, register tile 4 f32x2-pairs x 8 points ----
        {
            unsigned long long acc[WPTS][4];
#pragma unroll
            for (int p = 0; p < WPTS; p++)
#pragma unroll
                for (int j = 0; j < 4; j++) acc[p][j] = bias3[j];

#pragma unroll 2
            for (int k = 0; k < F2; k++) {
                unsigned long long wv[4];
#pragma unroll
                for (int j = 0; j < 4; j++)
                    wv[j] = ldb64(&s.w3[k][2 * lane + 64 * j]);
#pragma unroll
                for (int p = 0; p < WPTS; p++) {
                    const unsigned long long hh = pack2(s.h2[w][p][k]);
#pragma unroll
                    for (int j = 0; j < 4; j++) fma2(acc[p][j], wv[j], hh);
                }
            }

            // relu + masked running max
#pragma unroll
            for (int p = 0; p < WPTS; p++) {
                if (gw + p < len) {
#pragma unroll
                    for (int j = 0; j < 4; j++) {
                        m[2 * j]     = fmaxf(m[2 * j],     fmaxf(lo32(acc[p][j]), 0.0f));
                        m[2 * j + 1] = fmaxf(m[2 * j + 1], fmaxf(hi32(acc[p][j]), 0.0f));
                    }
                }
            }
        }
        __syncwarp();
    }

    // ---- block reduce over warps, then one atomicMax per feature ----
    __syncthreads();                       // everyone done with s.h1
    float* red = &s.h1[0][0][0];           // [WARPS][256]
#pragma unroll
    for (int j = 0; j < 4; j++) {
        red[w * F3 + 2 * lane + 64 * j]     = m[2 * j];
        red[w * F3 + 2 * lane + 64 * j + 1] = m[2 * j + 1];
    }
    __syncthreads();
    float v = red[tid];
#pragma unroll
    for (int ww = 1; ww < WARPS; ww++) v = fmaxf(v, red[ww * F3 + tid]);
    // all values >= 0: int compare == float compare
    atomicMax(reinterpret_cast<int*>(&g_agg[b * F3 + tid]), __float_as_int(v));
}

__global__ void __launch_bounds__(256)
rho_kernel(const float* __restrict__ r1w, const float* __restrict__ r1b,
           const float* __restrict__ r2w, const float* __restrict__ r2b,
           const float* __restrict__ r3w, const float* __restrict__ r3b,
           float* __restrict__ out)
{
    __shared__ float a[256], z1[256], z2[128];
    const int b   = blockIdx.x;
    const int tid = threadIdx.x;

    a[tid] = g_agg[b * F3 + tid];
    __syncthreads();

    float acc = r1b[tid];
#pragma unroll 4
    for (int k = 0; k < 256; k++) acc = fmaf(a[k], r1w[k * 256 + tid], acc);
    z1[tid] = fmaxf(acc, 0.0f);
    __syncthreads();

    if (tid < 128) {
        float acc2 = r2b[tid];
#pragma unroll 4
        for (int k = 0; k < 256; k++) acc2 = fmaf(z1[k], r2w[k * 128 + tid], acc2);
        z2[tid] = fmaxf(acc2, 0.0f);
    }
    __syncthreads();

    if (tid < 64) {
        float acc3 = r3b[tid];
#pragma unroll 4
        for (int k = 0; k < 128; k++) acc3 = fmaf(z2[k], r3w[k * 64 + tid], acc3);
        out[b * OUT + tid] = acc3;
    }
}

// ---------------- launch ----------------
extern "C" void kernel_launch(void* const* d_in, const int* in_sizes, int n_in,
                              void* d_out, int out_size)
{
    (void)in_sizes; (void)n_in; (void)out_size;
    const float* points = (const float*)d_in[0];
    const int*   lengths= (const int*)  d_in[1];
    const float* w1  = (const float*)d_in[2];
    const float* b1  = (const float*)d_in[3];
    const float* w2  = (const float*)d_in[4];
    const float* b2  = (const float*)d_in[5];
    const float* w3  = (const float*)d_in[6];
    const float* b3  = (const float*)d_in[7];
    const float* r1w = (const float*)d_in[8];
    const float* r1b = (const float*)d_in[9];
    const float* r2w = (const float*)d_in[10];
    const float* r2b = (const float*)d_in[11];
    const float* r3w = (const float*)d_in[12];
    const float* r3b = (const float*)d_in[13];

    cudaFuncSetAttribute(phi_kernel,
                         cudaFuncAttributeMaxDynamicSharedMemorySize,
                         (int)sizeof(Smem));

    init_agg_kernel<<<(B * F3 + 255) / 256, 256>>>();
    phi_kernel<<<dim3(BLOCKS_X, B), 256, sizeof(Smem)>>>(
        points, lengths, w1, b1, w2, b2, w3, b3);
    rho_kernel<<<B, 256>>>(r1w, r1b, r2w, r2b, r3w, r3b, (float*)d_out);
}

// round 4
// speedup vs baseline: 1.8024x; 1.8024x over previous
#include <cuda_runtime.h>
#include <cstdint>

// ---------------- problem constants ----------------
constexpr int B   = 128;
constexpr int N   = 4096;
constexpr int OUT = 64;
constexpr int F1 = 64, F2 = 128, F3 = 256;

constexpr int TILE  = 64;    // points per CTA-iteration
constexpr int TCTAS = 8;     // tile-CTAs per batch

// strides (floats) with +4 pad -> conflict-free fragment LDS
constexpr int S1 = 68;       // h1 / w2t rows (k-dim 64)
constexpr int S3 = 132;      // h2 / w3t rows (k-dim 128)

__device__ float g_agg[B * F3];

// smem layout (floats)
constexpr int OFF_W1  = 0;              // 128
constexpr int OFF_B1  = 128;            // 64
constexpr int OFF_B2  = 192;            // 128
constexpr int OFF_B3  = 320;            // 256
constexpr int OFF_SB  = 576;            // 256 (int col-max buffer)
constexpr int OFF_H1  = 832;            // 64*68   = 4352
constexpr int OFF_H2  = OFF_H1 + 64 * S1;      // 64*132  = 8448
constexpr int OFF_W2T = OFF_H2 + 64 * S3;      // 128*68  = 8704
constexpr int OFF_W3T = OFF_W2T + 128 * S1;    // 256*132 = 33792
constexpr int SMEM_FLOATS = OFF_W3T + 256 * S3;        // 56128 floats
constexpr int SMEM_TOTAL  = SMEM_FLOATS * 4;           // 224512 B

__device__ __forceinline__ float tf32r(float v) {
    uint32_t r;
    asm("cvt.rna.tf32.f32 %0, %1;" : "=r"(r) : "f"(v));
    return __uint_as_float(r);
}

__device__ __forceinline__ void mma_tf32(float* d,
                                         uint32_t a0, uint32_t a1, uint32_t a2, uint32_t a3,
                                         uint32_t b0, uint32_t b1) {
    asm volatile(
        "mma.sync.aligned.m16n8k8.row.col.f32.tf32.tf32.f32 "
        "{%0,%1,%2,%3}, {%4,%5,%6,%7}, {%8,%9}, {%0,%1,%2,%3};"
        : "+f"(d[0]), "+f"(d[1]), "+f"(d[2]), "+f"(d[3])
        : "r"(a0), "r"(a1), "r"(a2), "r"(a3), "r"(b0), "r"(b1));
}

// ---------------- kernels ----------------
__global__ void init_agg_kernel() {
    int i = blockIdx.x * blockDim.x + threadIdx.x;
    if (i < B * F3) g_agg[i] = 0.0f;
}

__global__ void __launch_bounds__(256, 1)
phi_mma_kernel(const float* __restrict__ points, const int* __restrict__ lengths,
               const float* __restrict__ w1, const float* __restrict__ b1,
               const float* __restrict__ w2, const float* __restrict__ b2,
               const float* __restrict__ w3, const float* __restrict__ b3)
{
    const int bidx = blockIdx.y;
    const int len  = lengths[bidx];
    if (blockIdx.x * TILE >= len) return;   // block-uniform early exit

    extern __shared__ float smf[];
    float* w1s = smf + OFF_W1;
    float* b1s = smf + OFF_B1;
    float* b2s = smf + OFF_B2;
    float* b3s = smf + OFF_B3;
    int*   sbf = reinterpret_cast<int*>(smf + OFF_SB);
    float* h1  = smf + OFF_H1;
    float* h2  = smf + OFF_H2;
    float* w2t = smf + OFF_W2T;
    float* w3t = smf + OFF_W3T;
    const uint32_t* h1u  = reinterpret_cast<const uint32_t*>(h1);
    const uint32_t* h2u  = reinterpret_cast<const uint32_t*>(h2);
    const uint32_t* w2tu = reinterpret_cast<const uint32_t*>(w2t);
    const uint32_t* w3tu = reinterpret_cast<const uint32_t*>(w3t);

    const int tid = threadIdx.x;

    // ---- stage weights (transposed [n][k], tf32-rounded) + params ----
    for (int i = tid; i < F1 * F2; i += 256) {       // w2: [64k][128n]
        int k = i >> 7, n = i & 127;
        w2t[n * S1 + k] = tf32r(w2[i]);
    }
    for (int i = tid; i < F2 * F3; i += 256) {       // w3: [128k][256n]
        int k = i >> 8, n = i & 255;
        w3t[n * S3 + k] = tf32r(w3[i]);
    }
    if (tid < 128) w1s[tid] = w1[tid];
    if (tid < 64)  b1s[tid] = b1[tid];
    if (tid < 128) b2s[tid] = b2[tid];
    b3s[tid] = b3[tid];
    sbf[tid] = 0;
    __syncthreads();

    const int lane = tid & 31;
    const int wid  = tid >> 5;
    const int mt   = wid & 3;          // m-tile (16 rows) within 64-pt tile
    const int nh   = wid >> 2;         // n-half
    const int g    = lane >> 2;        // row group 0..7
    const int c    = lane & 3;         // col-in-group 0..3
    const int mbase = mt * 16;

    float rm[16][2];                   // running max: [n-tile][col parity]
#pragma unroll
    for (int n = 0; n < 16; n++) { rm[n][0] = 0.0f; rm[n][1] = 0.0f; }

    for (int t = blockIdx.x; t * TILE < len; t += TCTAS) {
        // ---- layer 1: 2 -> 64 (thread: point tid>>2, feats (tid&3)*16..) ----
        {
            const int p  = tid >> 2;
            const int fb = (tid & 3) * 16;
            const int mg = t * TILE + p;
            float x = 0.0f, y = 0.0f;
            if (mg < len) {
                float2 pp = reinterpret_cast<const float2*>(points)[(long long)bidx * N + mg];
                x = pp.x; y = pp.y;
            }
#pragma unroll
            for (int i = 0; i < 16; i++) {
                int f = fb + i;
                float v = fmaxf(fmaf(x, w1s[f], fmaf(y, w1s[64 + f], b1s[f])), 0.0f);
                h1[p * S1 + f] = tf32r(v);
            }
        }
        __syncthreads();

        // ---- layer 2: [64x64] @ [64x128] -> h2, warp covers 16m x 64n ----
        {
            float acc[8][4];
#pragma unroll
            for (int n = 0; n < 8; n++)
#pragma unroll
                for (int j = 0; j < 4; j++) acc[n][j] = 0.0f;

#pragma unroll
            for (int k = 0; k < 8; k++) {
                const int ar = (mbase + g) * S1 + k * 8 + c;
                uint32_t a0 = h1u[ar];
                uint32_t a1 = h1u[ar + 8 * S1];
                uint32_t a2 = h1u[ar + 4];
                uint32_t a3 = h1u[ar + 8 * S1 + 4];
#pragma unroll
                for (int n = 0; n < 8; n++) {
                    const int br = (nh * 64 + n * 8 + g) * S1 + k * 8 + c;
                    mma_tf32(acc[n], a0, a1, a2, a3, w2tu[br], w2tu[br + 4]);
                }
            }
            // epilogue: bias + relu + tf32 -> h2[m][n]
            const int row0 = mbase + g, row1 = row0 + 8;
#pragma unroll
            for (int n = 0; n < 8; n++) {
                const int col = nh * 64 + n * 8 + 2 * c;
                h2[row0 * S3 + col]     = tf32r(fmaxf(acc[n][0] + b2s[col], 0.0f));
                h2[row0 * S3 + col + 1] = tf32r(fmaxf(acc[n][1] + b2s[col + 1], 0.0f));
                h2[row1 * S3 + col]     = tf32r(fmaxf(acc[n][2] + b2s[col], 0.0f));
                h2[row1 * S3 + col + 1] = tf32r(fmaxf(acc[n][3] + b2s[col + 1], 0.0f));
            }
        }
        __syncthreads();

        // ---- layer 3: [64x128] @ [128x256], warp covers 16m x 128n ----
        {
            float acc[16][4];
#pragma unroll
            for (int n = 0; n < 16; n++)
#pragma unroll
                for (int j = 0; j < 4; j++) acc[n][j] = 0.0f;

#pragma unroll 4
            for (int k = 0; k < 16; k++) {
                const int ar = (mbase + g) * S3 + k * 8 + c;
                uint32_t a0 = h2u[ar];
                uint32_t a1 = h2u[ar + 8 * S3];
                uint32_t a2 = h2u[ar + 4];
                uint32_t a3 = h2u[ar + 8 * S3 + 4];
#pragma unroll
                for (int n = 0; n < 16; n++) {
                    const int br = (nh * 128 + n * 8 + g) * S3 + k * 8 + c;
                    mma_tf32(acc[n], a0, a1, a2, a3, w3tu[br], w3tu[br + 4]);
                }
            }

            // epilogue: bias + relu + mask + running max
            const int r0 = t * TILE + mbase + g;
            const int r1 = r0 + 8;
            const bool v0 = r0 < len, v1 = r1 < len;
#pragma unroll
            for (int n = 0; n < 16; n++) {
                const int col = nh * 128 + n * 8 + 2 * c;
                const float bb0 = b3s[col], bb1 = b3s[col + 1];
                float x0 = v0 ? fmaxf(acc[n][0] + bb0, 0.0f) : 0.0f;
                float x1 = v0 ? fmaxf(acc[n][1] + bb1, 0.0f) : 0.0f;
                float y0 = v1 ? fmaxf(acc[n][2] + bb0, 0.0f) : 0.0f;
                float y1 = v1 ? fmaxf(acc[n][3] + bb1, 0.0f) : 0.0f;
                rm[n][0] = fmaxf(rm[n][0], fmaxf(x0, y0));
                rm[n][1] = fmaxf(rm[n][1], fmaxf(x1, y1));
            }
        }
        __syncthreads();   // h1/h2 reused next iteration
    }

    // ---- reduce running max across row groups, then CTA cols, then global ----
#pragma unroll
    for (int n = 0; n < 16; n++) {
#pragma unroll
        for (int j = 0; j < 2; j++) {
            float v = rm[n][j];
            v = fmaxf(v, __shfl_xor_sync(0xFFFFFFFFu, v, 4));
            v = fmaxf(v, __shfl_xor_sync(0xFFFFFFFFu, v, 8));
            v = fmaxf(v, __shfl_xor_sync(0xFFFFFFFFu, v, 16));
            if (g == 0)
                atomicMax(&sbf[nh * 128 + n * 8 + 2 * c + j], __float_as_int(v));
        }
    }
    __syncthreads();
    atomicMax(reinterpret_cast<int*>(&g_agg[bidx * F3 + tid]), sbf[tid]);
}

__global__ void __launch_bounds__(256)
rho_kernel(const float* __restrict__ r1w, const float* __restrict__ r1b,
           const float* __restrict__ r2w, const float* __restrict__ r2b,
           const float* __restrict__ r3w, const float* __restrict__ r3b,
           float* __restrict__ out)
{
    __shared__ float a[256], z1[256], z2[128];
    const int b   = blockIdx.x;
    const int tid = threadIdx.x;

    a[tid] = g_agg[b * F3 + tid];
    __syncthreads();

    float acc = r1b[tid];
#pragma unroll 4
    for (int k = 0; k < 256; k++) acc = fmaf(a[k], r1w[k * 256 + tid], acc);
    z1[tid] = fmaxf(acc, 0.0f);
    __syncthreads();

    if (tid < 128) {
        float acc2 = r2b[tid];
#pragma unroll 4
        for (int k = 0; k < 256; k++) acc2 = fmaf(z1[k], r2w[k * 128 + tid], acc2);
        z2[tid] = fmaxf(acc2, 0.0f);
    }
    __syncthreads();

    if (tid < 64) {
        float acc3 = r3b[tid];
#pragma unroll 4
        for (int k = 0; k < 128; k++) acc3 = fmaf(z2[k], r3w[k * 64 + tid], acc3);
        out[b * OUT + tid] = acc3;
    }
}

// ---------------- launch ----------------
extern "C" void kernel_launch(void* const* d_in, const int* in_sizes, int n_in,
                              void* d_out, int out_size)
{
    (void)in_sizes; (void)n_in; (void)out_size;
    const float* points = (const float*)d_in[0];
    const int*   lengths= (const int*)  d_in[1];
    const float* w1  = (const float*)d_in[2];
    const float* b1  = (const float*)d_in[3];
    const float* w2  = (const float*)d_in[4];
    const float* b2  = (const float*)d_in[5];
    const float* w3  = (const float*)d_in[6];
    const float* b3  = (const float*)d_in[7];
    const float* r1w = (const float*)d_in[8];
    const float* r1b = (const float*)d_in[9];
    const float* r2w = (const float*)d_in[10];
    const float* r2b = (const float*)d_in[11];
    const float* r3w = (const float*)d_in[12];
    const float* r3b = (const float*)d_in[13];

    cudaFuncSetAttribute(phi_mma_kernel,
                         cudaFuncAttributeMaxDynamicSharedMemorySize, SMEM_TOTAL);

    init_agg_kernel<<<(B * F3 + 255) / 256, 256>>>();
    phi_mma_kernel<<<dim3(TCTAS, B), 256, SMEM_TOTAL>>>(
        points, lengths, w1, b1, w2, b2, w3, b3);
    rho_kernel<<<B, 256>>>(r1w, r1b, r2w, r2b, r3w, r3b, (float*)d_out);
}

// round 5
// speedup vs baseline: 2.0446x; 1.1344x over previous
#include <cuda_runtime.h>
#include <cstdint>

// ---------------- problem constants ----------------
constexpr int B   = 128;
constexpr int N   = 4096;
constexpr int OUT = 64;
constexpr int F1 = 64, F2 = 128, F3 = 256;

constexpr int TILE  = 64;    // points per CTA-iteration
constexpr int TCTAS = 8;     // tile-CTAs per batch

// strides (floats) with +4 pad -> conflict-free fragment LDS
constexpr int S1 = 68;       // h1 / w2t rows (k-dim 64)
constexpr int S3 = 132;      // h2 / w3t rows (k-dim 128)

__device__ float g_agg[B * F3];

// smem layout (floats)
constexpr int OFF_W1  = 0;              // 128
constexpr int OFF_B1  = 128;            // 64
constexpr int OFF_B2  = 192;            // 128
constexpr int OFF_B3  = 320;            // 256
constexpr int OFF_H1  = 832;            // 64*68   = 4352
constexpr int OFF_H2  = OFF_H1 + 64 * S1;      // 64*132  = 8448
constexpr int OFF_W2T = OFF_H2 + 64 * S3;      // 128*68  = 8704
constexpr int OFF_W3T = OFF_W2T + 128 * S1;    // 256*132 = 33792
constexpr int SMEM_FLOATS = OFF_W3T + 256 * S3;        // 56128 floats
constexpr int SMEM_TOTAL  = SMEM_FLOATS * 4;           // 224512 B

__device__ __forceinline__ float tf32r(float v) {
    uint32_t r;
    asm("cvt.rna.tf32.f32 %0, %1;" : "=r"(r) : "f"(v));
    return __uint_as_float(r);
}

__device__ __forceinline__ void mma_tf32(float* d,
                                         uint32_t a0, uint32_t a1, uint32_t a2, uint32_t a3,
                                         uint32_t b0, uint32_t b1) {
    asm volatile(
        "mma.sync.aligned.m16n8k8.row.col.f32.tf32.tf32.f32 "
        "{%0,%1,%2,%3}, {%4,%5,%6,%7}, {%8,%9}, {%0,%1,%2,%3};"
        : "+f"(d[0]), "+f"(d[1]), "+f"(d[2]), "+f"(d[3])
        : "r"(a0), "r"(a1), "r"(a2), "r"(a3), "r"(b0), "r"(b1));
}

// ---------------- kernels ----------------
__global__ void init_agg_kernel() {
    int i = blockIdx.x * blockDim.x + threadIdx.x;
    if (i < B * F3) g_agg[i] = 0.0f;
}

__global__ void __launch_bounds__(256, 1)
phi_mma_kernel(const float* __restrict__ points, const int* __restrict__ lengths,
               const float* __restrict__ w1, const float* __restrict__ b1,
               const float* __restrict__ w2, const float* __restrict__ b2,
               const float* __restrict__ w3, const float* __restrict__ b3)
{
    const int bidx = blockIdx.y;
    const int len  = lengths[bidx];
    if (blockIdx.x * TILE >= len) return;   // block-uniform early exit

    extern __shared__ float smf[];
    float* w1s = smf + OFF_W1;
    float* b1s = smf + OFF_B1;
    float* b2s = smf + OFF_B2;
    float* b3s = smf + OFF_B3;
    float* h1  = smf + OFF_H1;
    float* h2  = smf + OFF_H2;
    float* w2t = smf + OFF_W2T;
    float* w3t = smf + OFF_W3T;
    const uint32_t* h1u  = reinterpret_cast<const uint32_t*>(h1);
    const uint32_t* h2u  = reinterpret_cast<const uint32_t*>(h2);
    const uint32_t* w2tu = reinterpret_cast<const uint32_t*>(w2t);
    const uint32_t* w3tu = reinterpret_cast<const uint32_t*>(w3t);

    const int tid = threadIdx.x;

    // ---- stage weights (transposed [n][k], tf32-rounded) + params ----
    for (int i = tid; i < F1 * F2; i += 256) {       // w2: [64k][128n]
        int k = i >> 7, n = i & 127;
        w2t[n * S1 + k] = tf32r(w2[i]);
    }
    for (int i = tid; i < F2 * F3; i += 256) {       // w3: [128k][256n]
        int k = i >> 8, n = i & 255;
        w3t[n * S3 + k] = tf32r(w3[i]);
    }
    if (tid < 128) w1s[tid] = w1[tid];
    if (tid < 64)  b1s[tid] = b1[tid];
    if (tid < 128) b2s[tid] = b2[tid];
    b3s[tid] = b3[tid];
    __syncthreads();

    const int lane = tid & 31;
    const int wid  = tid >> 5;
    const int g    = lane >> 2;        // row group 0..7
    const int c    = lane & 3;         // col-in-group 0..3
    const int nb2  = wid * 16;         // this warp's L2 n-slice base
    const int nb3  = wid * 32;         // this warp's L3 n-slice base

    // ---- persistent B fragments (loaded once per CTA) ----
    float b2r[2][8][2];
#pragma unroll
    for (int nt = 0; nt < 2; nt++)
#pragma unroll
        for (int k = 0; k < 8; k++) {
            const int br = (nb2 + nt * 8 + g) * S1 + k * 8 + c;
            b2r[nt][k][0] = w2t[br];
            b2r[nt][k][1] = w2t[br + 4];
        }
    float b3r[4][16][2];
#pragma unroll
    for (int nt = 0; nt < 4; nt++)
#pragma unroll
        for (int k = 0; k < 16; k++) {
            const int br = (nb3 + nt * 8 + g) * S3 + k * 8 + c;
            b3r[nt][k][0] = w3t[br];
            b3r[nt][k][1] = w3t[br + 4];
        }
    // per-thread bias registers (fixed output columns)
    float bb2[2][2], bb3[4][2];
#pragma unroll
    for (int nt = 0; nt < 2; nt++) {
        bb2[nt][0] = b2s[nb2 + nt * 8 + 2 * c];
        bb2[nt][1] = b2s[nb2 + nt * 8 + 2 * c + 1];
    }
#pragma unroll
    for (int nt = 0; nt < 4; nt++) {
        bb3[nt][0] = b3s[nb3 + nt * 8 + 2 * c];
        bb3[nt][1] = b3s[nb3 + nt * 8 + 2 * c + 1];
    }

    float rm[4][2];                    // running max for this thread's cols
#pragma unroll
    for (int nt = 0; nt < 4; nt++) { rm[nt][0] = 0.0f; rm[nt][1] = 0.0f; }

    for (int t = blockIdx.x; t * TILE < len; t += TCTAS) {
        // ---- layer 1: 2 -> 64. thread: point tid>>2, feats f = (tid&3)+4i ----
        {
            const int p  = tid >> 2;
            const int cl = tid & 3;
            const int mg = t * TILE + p;
            float x = 0.0f, y = 0.0f;
            if (mg < len) {
                float2 pp = reinterpret_cast<const float2*>(points)[(long long)bidx * N + mg];
                x = pp.x; y = pp.y;
            }
#pragma unroll
            for (int i = 0; i < 16; i++) {
                const int f = cl + 4 * i;     // conflict-free store bank = 4p+cl
                float v = fmaxf(fmaf(x, w1s[f], fmaf(y, w1s[64 + f], b1s[f])), 0.0f);
                h1[p * S1 + f] = tf32r(v);
            }
        }
        __syncthreads();

        // ---- layer 2: warp covers all 64m x its 16n; B from registers ----
#pragma unroll
        for (int mf = 0; mf < 4; mf++) {
            float acc[2][4];
#pragma unroll
            for (int nt = 0; nt < 2; nt++)
#pragma unroll
                for (int j = 0; j < 4; j++) acc[nt][j] = 0.0f;

#pragma unroll
            for (int k = 0; k < 8; k++) {
                const int ar = (mf * 16 + g) * S1 + k * 8 + c;
                uint32_t a0 = h1u[ar];
                uint32_t a1 = h1u[ar + 8 * S1];
                uint32_t a2 = h1u[ar + 4];
                uint32_t a3 = h1u[ar + 8 * S1 + 4];
#pragma unroll
                for (int nt = 0; nt < 2; nt++)
                    mma_tf32(acc[nt], a0, a1, a2, a3,
                             __float_as_uint(b2r[nt][k][0]), __float_as_uint(b2r[nt][k][1]));
            }
            const int r0 = mf * 16 + g, r1 = r0 + 8;
#pragma unroll
            for (int nt = 0; nt < 2; nt++) {
                const int col = nb2 + nt * 8 + 2 * c;
                *reinterpret_cast<float2*>(&h2[r0 * S3 + col]) =
                    make_float2(tf32r(fmaxf(acc[nt][0] + bb2[nt][0], 0.0f)),
                                tf32r(fmaxf(acc[nt][1] + bb2[nt][1], 0.0f)));
                *reinterpret_cast<float2*>(&h2[r1 * S3 + col]) =
                    make_float2(tf32r(fmaxf(acc[nt][2] + bb2[nt][0], 0.0f)),
                                tf32r(fmaxf(acc[nt][3] + bb2[nt][1], 0.0f)));
            }
        }
        __syncthreads();

        // ---- layer 3: warp covers all 64m x its 32n; B from registers ----
#pragma unroll
        for (int mf = 0; mf < 4; mf++) {
            float acc[4][4];
#pragma unroll
            for (int nt = 0; nt < 4; nt++)
#pragma unroll
                for (int j = 0; j < 4; j++) acc[nt][j] = 0.0f;

#pragma unroll
            for (int k = 0; k < 16; k++) {
                const int ar = (mf * 16 + g) * S3 + k * 8 + c;
                uint32_t a0 = h2u[ar];
                uint32_t a1 = h2u[ar + 8 * S3];
                uint32_t a2 = h2u[ar + 4];
                uint32_t a3 = h2u[ar + 8 * S3 + 4];
#pragma unroll
                for (int nt = 0; nt < 4; nt++)
                    mma_tf32(acc[nt], a0, a1, a2, a3,
                             __float_as_uint(b3r[nt][k][0]), __float_as_uint(b3r[nt][k][1]));
            }
            // epilogue: bias + relu + validity mask + running max (registers only)
            const int r0 = t * TILE + mf * 16 + g;
            const int r1 = r0 + 8;
            const bool v0 = r0 < len, v1 = r1 < len;
#pragma unroll
            for (int nt = 0; nt < 4; nt++) {
                float x0 = v0 ? fmaxf(acc[nt][0] + bb3[nt][0], 0.0f) : 0.0f;
                float x1 = v0 ? fmaxf(acc[nt][1] + bb3[nt][1], 0.0f) : 0.0f;
                float y0 = v1 ? fmaxf(acc[nt][2] + bb3[nt][0], 0.0f) : 0.0f;
                float y1 = v1 ? fmaxf(acc[nt][3] + bb3[nt][1], 0.0f) : 0.0f;
                rm[nt][0] = fmaxf(rm[nt][0], fmaxf(x0, y0));
                rm[nt][1] = fmaxf(rm[nt][1], fmaxf(x1, y1));
            }
        }
        __syncthreads();   // h1/h2 reused next iteration
    }

    // ---- reduce over row-groups (lane strides 4,8,16); cols disjoint per warp ----
#pragma unroll
    for (int nt = 0; nt < 4; nt++) {
#pragma unroll
        for (int j = 0; j < 2; j++) {
            float v = rm[nt][j];
            v = fmaxf(v, __shfl_xor_sync(0xFFFFFFFFu, v, 4));
            v = fmaxf(v, __shfl_xor_sync(0xFFFFFFFFu, v, 8));
            v = fmaxf(v, __shfl_xor_sync(0xFFFFFFFFu, v, 16));
            if (g == 0)
                atomicMax(reinterpret_cast<int*>(&g_agg[bidx * F3 + nb3 + nt * 8 + 2 * c + j]),
                          __float_as_int(v));
        }
    }
}

__global__ void __launch_bounds__(256)
rho_kernel(const float* __restrict__ r1w, const float* __restrict__ r1b,
           const float* __restrict__ r2w, const float* __restrict__ r2b,
           const float* __restrict__ r3w, const float* __restrict__ r3b,
           float* __restrict__ out)
{
    __shared__ float a[256], z1[256], z2[128];
    const int b   = blockIdx.x;
    const int tid = threadIdx.x;

    a[tid] = g_agg[b * F3 + tid];
    __syncthreads();

    float acc = r1b[tid];
#pragma unroll 4
    for (int k = 0; k < 256; k++) acc = fmaf(a[k], r1w[k * 256 + tid], acc);
    z1[tid] = fmaxf(acc, 0.0f);
    __syncthreads();

    if (tid < 128) {
        float acc2 = r2b[tid];
#pragma unroll 4
        for (int k = 0; k < 256; k++) acc2 = fmaf(z1[k], r2w[k * 128 + tid], acc2);
        z2[tid] = fmaxf(acc2, 0.0f);
    }
    __syncthreads();

    if (tid < 64) {
        float acc3 = r3b[tid];
#pragma unroll 4
        for (int k = 0; k < 128; k++) acc3 = fmaf(z2[k], r3w[k * 64 + tid], acc3);
        out[b * OUT + tid] = acc3;
    }
}

// ---------------- launch ----------------
extern "C" void kernel_launch(void* const* d_in, const int* in_sizes, int n_in,
                              void* d_out, int out_size)
{
    (void)in_sizes; (void)n_in; (void)out_size;
    const float* points = (const float*)d_in[0];
    const int*   lengths= (const int*)  d_in[1];
    const float* w1  = (const float*)d_in[2];
    const float* b1  = (const float*)d_in[3];
    const float* w2  = (const float*)d_in[4];
    const float* b2  = (const float*)d_in[5];
    const float* w3  = (const float*)d_in[6];
    const float* b3  = (const float*)d_in[7];
    const float* r1w = (const float*)d_in[8];
    const float* r1b = (const float*)d_in[9];
    const float* r2w = (const float*)d_in[10];
    const float* r2b = (const float*)d_in[11];
    const float* r3w = (const float*)d_in[12];
    const float* r3b = (const float*)d_in[13];

    cudaFuncSetAttribute(phi_mma_kernel,
                         cudaFuncAttributeMaxDynamicSharedMemorySize, SMEM_TOTAL);

    init_agg_kernel<<<(B * F3 + 255) / 256, 256>>>();
    phi_mma_kernel<<<dim3(TCTAS, B), 256, SMEM_TOTAL>>>(
        points, lengths, w1, b1, w2, b2, w3, b3);
    rho_kernel<<<B, 256>>>(r1w, r1b, r2w, r2b, r3w, r3b, (float*)d_out);
}

// round 6
// speedup vs baseline: 2.1578x; 1.0554x over previous
#include <cuda_runtime.h>
#include <cstdint>

// ---------------- problem constants ----------------
constexpr int B   = 128;
constexpr int N   = 4096;
constexpr int OUT = 64;
constexpr int F1 = 64, F2 = 128, F3 = 256;

constexpr int TILE  = 128;   // points per CTA-iteration
constexpr int TCTAS = 8;     // tile-CTAs per batch

// strides (floats) with +4 pad -> conflict-free fragment LDS
constexpr int S1 = 68;       // h1 / w2t rows (k-dim 64)
constexpr int S3 = 132;      // h2 / w3t rows (k-dim 128)

__device__ float g_agg[B * F3];

// ---------------- smem layout (floats) ----------------
constexpr int OFF_W1  = 0;              // 128
constexpr int OFF_B1  = 128;            // 64
constexpr int OFF_B2  = 192;            // 128
constexpr int OFF_B3  = 320;            // 256
constexpr int OFF_R   = 576;            // overlay region
// phase 1 (weight staging):
constexpr int OFF_W2T = OFF_R;                   // 128*68  = 8704
constexpr int OFF_W3T = OFF_R + 128 * S1;        // 256*132 = 33792
// phase 2 (reuse as activation buffers):
constexpr int OFF_H1A = OFF_R;                   // 128*68 = 8704
constexpr int OFF_H1B = OFF_R + TILE * S1;       // 8704
constexpr int OFF_H2  = OFF_R + 2 * TILE * S1;   // 128*132 = 16896
constexpr int SMEM_FLOATS = OFF_R + 128 * S1 + 256 * S3;   // 43072
constexpr int SMEM_TOTAL  = SMEM_FLOATS * 4;               // 172288 B

__device__ __forceinline__ float tf32r(float v) {
    uint32_t r;
    asm("cvt.rna.tf32.f32 %0, %1;" : "=r"(r) : "f"(v));
    return __uint_as_float(r);
}

__device__ __forceinline__ void mma_tf32(float* d,
                                         uint32_t a0, uint32_t a1, uint32_t a2, uint32_t a3,
                                         uint32_t b0, uint32_t b1) {
    asm volatile(
        "mma.sync.aligned.m16n8k8.row.col.f32.tf32.tf32.f32 "
        "{%0,%1,%2,%3}, {%4,%5,%6,%7}, {%8,%9}, {%0,%1,%2,%3};"
        : "+f"(d[0]), "+f"(d[1]), "+f"(d[2]), "+f"(d[3])
        : "r"(a0), "r"(a1), "r"(a2), "r"(a3), "r"(b0), "r"(b1));
}

// ---------------- kernels ----------------
__global__ void init_agg_kernel() {
    int i = blockIdx.x * blockDim.x + threadIdx.x;
    if (i < B * F3) g_agg[i] = 0.0f;
}

__global__ void __launch_bounds__(256, 1)
phi_mma_kernel(const float* __restrict__ points, const int* __restrict__ lengths,
               const float* __restrict__ w1, const float* __restrict__ b1,
               const float* __restrict__ w2, const float* __restrict__ b2,
               const float* __restrict__ w3, const float* __restrict__ b3)
{
    const int bidx = blockIdx.y;
    const int len  = lengths[bidx];
    if (blockIdx.x * TILE >= len) return;   // block-uniform early exit

    extern __shared__ float smf[];
    float* w1s = smf + OFF_W1;
    float* b1s = smf + OFF_B1;
    float* b2s = smf + OFF_B2;
    float* b3s = smf + OFF_B3;
    float* w2t = smf + OFF_W2T;
    float* w3t = smf + OFF_W3T;
    float* h1a = smf + OFF_H1A;
    float* h1b = smf + OFF_H1B;
    float* h2  = smf + OFF_H2;
    const uint32_t* h2u = reinterpret_cast<const uint32_t*>(h2);

    const int tid = threadIdx.x;

    // ---- phase 1: stage weights (transposed [n][k], tf32) + params ----
    for (int i = tid; i < F1 * F2; i += 256) {       // w2: [64k][128n]
        int k = i >> 7, n = i & 127;
        w2t[n * S1 + k] = tf32r(w2[i]);
    }
    for (int i = tid; i < F2 * F3; i += 256) {       // w3: [128k][256n]
        int k = i >> 8, n = i & 255;
        w3t[n * S3 + k] = tf32r(w3[i]);
    }
    if (tid < 128) w1s[tid] = w1[tid];
    if (tid < 64)  b1s[tid] = b1[tid];
    if (tid < 128) b2s[tid] = b2[tid];
    b3s[tid] = b3[tid];
    __syncthreads();

    const int lane = tid & 31;
    const int wid  = tid >> 5;
    const int g    = lane >> 2;        // row group 0..7
    const int c    = lane & 3;         // col-in-group 0..3
    const int nb2  = wid * 16;         // this warp's L2 n-slice base
    const int nb3  = wid * 32;         // this warp's L3 n-slice base

    // ---- persistent B fragments + biases (registers) ----
    float b2r[2][8][2];
#pragma unroll
    for (int nt = 0; nt < 2; nt++)
#pragma unroll
        for (int k = 0; k < 8; k++) {
            const int br = (nb2 + nt * 8 + g) * S1 + k * 8 + c;
            b2r[nt][k][0] = w2t[br];
            b2r[nt][k][1] = w2t[br + 4];
        }
    float b3r[4][16][2];
#pragma unroll
    for (int nt = 0; nt < 4; nt++)
#pragma unroll
        for (int k = 0; k < 16; k++) {
            const int br = (nb3 + nt * 8 + g) * S3 + k * 8 + c;
            b3r[nt][k][0] = w3t[br];
            b3r[nt][k][1] = w3t[br + 4];
        }
    float bb2[2][2], bb3[4][2];
#pragma unroll
    for (int nt = 0; nt < 2; nt++) {
        bb2[nt][0] = b2s[nb2 + nt * 8 + 2 * c];
        bb2[nt][1] = b2s[nb2 + nt * 8 + 2 * c + 1];
    }
#pragma unroll
    for (int nt = 0; nt < 4; nt++) {
        bb3[nt][0] = b3s[nb3 + nt * 8 + 2 * c];
        bb3[nt][1] = b3s[nb3 + nt * 8 + 2 * c + 1];
    }
    __syncthreads();      // weight smem region now dead -> reuse for h buffers

    float rm[4][2];
#pragma unroll
    for (int nt = 0; nt < 4; nt++) { rm[nt][0] = 0.0f; rm[nt][1] = 0.0f; }

    // ---- L1 producer: 2 -> 64 for tile tt into buffer h1buf ----
    auto do_L1 = [&](int tt, float* __restrict__ h1buf) {
        if (tt * TILE >= len) return;
        const int cl = tid & 3;
#pragma unroll
        for (int r = 0; r < 2; r++) {
            const int p  = (tid >> 2) + r * 64;
            const int mg = tt * TILE + p;
            float x = 0.0f, y = 0.0f;
            if (mg < len) {
                float2 pp = reinterpret_cast<const float2*>(points)[(long long)bidx * N + mg];
                x = pp.x; y = pp.y;
            }
#pragma unroll
            for (int i = 0; i < 16; i++) {
                const int f = cl + 4 * i;   // conflict-free store pattern
                float v = fmaxf(fmaf(x, w1s[f], fmaf(y, w1s[64 + f], b1s[f])), 0.0f);
                h1buf[p * S1 + f] = tf32r(v);
            }
        }
    };

    do_L1(blockIdx.x, h1a);
    __syncthreads();

    int it = 0;
    for (int t = blockIdx.x; t * TILE < len; t += TCTAS, it++) {
        float* h1cur = (it & 1) ? h1b : h1a;
        float* h1nxt = (it & 1) ? h1a : h1b;
        const uint32_t* h1u = reinterpret_cast<const uint32_t*>(h1cur);

        // ---- layer 2: all 128m x this warp's 16n; B in registers ----
#pragma unroll
        for (int mf = 0; mf < 8; mf++) {
            float acc[2][4];
#pragma unroll
            for (int nt = 0; nt < 2; nt++)
#pragma unroll
                for (int j = 0; j < 4; j++) acc[nt][j] = 0.0f;

#pragma unroll
            for (int k = 0; k < 8; k++) {
                const int ar = (mf * 16 + g) * S1 + k * 8 + c;
                uint32_t a0 = h1u[ar];
                uint32_t a1 = h1u[ar + 8 * S1];
                uint32_t a2 = h1u[ar + 4];
                uint32_t a3 = h1u[ar + 8 * S1 + 4];
#pragma unroll
                for (int nt = 0; nt < 2; nt++)
                    mma_tf32(acc[nt], a0, a1, a2, a3,
                             __float_as_uint(b2r[nt][k][0]), __float_as_uint(b2r[nt][k][1]));
            }
            const int r0 = mf * 16 + g, r1 = r0 + 8;
#pragma unroll
            for (int nt = 0; nt < 2; nt++) {
                const int col = nb2 + nt * 8 + 2 * c;
                *reinterpret_cast<float2*>(&h2[r0 * S3 + col]) =
                    make_float2(tf32r(fmaxf(acc[nt][0] + bb2[nt][0], 0.0f)),
                                tf32r(fmaxf(acc[nt][1] + bb2[nt][1], 0.0f)));
                *reinterpret_cast<float2*>(&h2[r1 * S3 + col]) =
                    make_float2(tf32r(fmaxf(acc[nt][2] + bb2[nt][0], 0.0f)),
                                tf32r(fmaxf(acc[nt][3] + bb2[nt][1], 0.0f)));
            }
        }

        // ---- L1 for next tile (overlaps with other warps' L2) ----
        do_L1(t + TCTAS, h1nxt);
        __syncthreads();            // h2 complete; h1nxt complete

        // ---- layer 3: all 128m x this warp's 32n; B in registers ----
#pragma unroll
        for (int mf = 0; mf < 8; mf++) {
            float acc[4][4];
#pragma unroll
            for (int nt = 0; nt < 4; nt++)
#pragma unroll
                for (int j = 0; j < 4; j++) acc[nt][j] = 0.0f;

#pragma unroll
            for (int k = 0; k < 16; k++) {
                const int ar = (mf * 16 + g) * S3 + k * 8 + c;
                uint32_t a0 = h2u[ar];
                uint32_t a1 = h2u[ar + 8 * S3];
                uint32_t a2 = h2u[ar + 4];
                uint32_t a3 = h2u[ar + 8 * S3 + 4];
#pragma unroll
                for (int nt = 0; nt < 4; nt++)
                    mma_tf32(acc[nt], a0, a1, a2, a3,
                             __float_as_uint(b3r[nt][k][0]), __float_as_uint(b3r[nt][k][1]));
            }
            // epilogue: bias + relu + validity mask + running max
            const int r0 = t * TILE + mf * 16 + g;
            const int r1 = r0 + 8;
            const bool v0 = r0 < len, v1 = r1 < len;
#pragma unroll
            for (int nt = 0; nt < 4; nt++) {
                float x0 = v0 ? fmaxf(acc[nt][0] + bb3[nt][0], 0.0f) : 0.0f;
                float x1 = v0 ? fmaxf(acc[nt][1] + bb3[nt][1], 0.0f) : 0.0f;
                float y0 = v1 ? fmaxf(acc[nt][2] + bb3[nt][0], 0.0f) : 0.0f;
                float y1 = v1 ? fmaxf(acc[nt][3] + bb3[nt][1], 0.0f) : 0.0f;
                rm[nt][0] = fmaxf(rm[nt][0], fmaxf(x0, y0));
                rm[nt][1] = fmaxf(rm[nt][1], fmaxf(x1, y1));
            }
        }
        __syncthreads();            // h2 free for next L2
    }

    // ---- reduce over row-groups; cols disjoint per warp -> direct atomic ----
#pragma unroll
    for (int nt = 0; nt < 4; nt++) {
#pragma unroll
        for (int j = 0; j < 2; j++) {
            float v = rm[nt][j];
            v = fmaxf(v, __shfl_xor_sync(0xFFFFFFFFu, v, 4));
            v = fmaxf(v, __shfl_xor_sync(0xFFFFFFFFu, v, 8));
            v = fmaxf(v, __shfl_xor_sync(0xFFFFFFFFu, v, 16));
            if (g == 0)
                atomicMax(reinterpret_cast<int*>(&g_agg[bidx * F3 + nb3 + nt * 8 + 2 * c + j]),
                          __float_as_int(v));
        }
    }
}

__global__ void __launch_bounds__(256)
rho_kernel(const float* __restrict__ r1w, const float* __restrict__ r1b,
           const float* __restrict__ r2w, const float* __restrict__ r2b,
           const float* __restrict__ r3w, const float* __restrict__ r3b,
           float* __restrict__ out)
{
    __shared__ float a[256], z1[256], z2[128];
    const int b   = blockIdx.x;
    const int tid = threadIdx.x;

    a[tid] = g_agg[b * F3 + tid];
    __syncthreads();

    float acc = r1b[tid];
#pragma unroll 4
    for (int k = 0; k < 256; k++) acc = fmaf(a[k], r1w[k * 256 + tid], acc);
    z1[tid] = fmaxf(acc, 0.0f);
    __syncthreads();

    if (tid < 128) {
        float acc2 = r2b[tid];
#pragma unroll 4
        for (int k = 0; k < 256; k++) acc2 = fmaf(z1[k], r2w[k * 128 + tid], acc2);
        z2[tid] = fmaxf(acc2, 0.0f);
    }
    __syncthreads();

    if (tid < 64) {
        float acc3 = r3b[tid];
#pragma unroll 4
        for (int k = 0; k < 128; k++) acc3 = fmaf(z2[k], r3w[k * 64 + tid], acc3);
        out[b * OUT + tid] = acc3;
    }
}

// ---------------- launch ----------------
extern "C" void kernel_launch(void* const* d_in, const int* in_sizes, int n_in,
                              void* d_out, int out_size)
{
    (void)in_sizes; (void)n_in; (void)out_size;
    const float* points = (const float*)d_in[0];
    const int*   lengths= (const int*)  d_in[1];
    const float* w1  = (const float*)d_in[2];
    const float* b1  = (const float*)d_in[3];
    const float* w2  = (const float*)d_in[4];
    const float* b2  = (const float*)d_in[5];
    const float* w3  = (const float*)d_in[6];
    const float* b3  = (const float*)d_in[7];
    const float* r1w = (const float*)d_in[8];
    const float* r1b = (const float*)d_in[9];
    const float* r2w = (const float*)d_in[10];
    const float* r2b = (const float*)d_in[11];
    const float* r3w = (const float*)d_in[12];
    const float* r3b = (const float*)d_in[13];

    cudaFuncSetAttribute(phi_mma_kernel,
                         cudaFuncAttributeMaxDynamicSharedMemorySize, SMEM_TOTAL);

    init_agg_kernel<<<(B * F3 + 255) / 256, 256>>>();
    phi_mma_kernel<<<dim3(TCTAS, B), 256, SMEM_TOTAL>>>(
        points, lengths, w1, b1, w2, b2, w3, b3);
    rho_kernel<<<B, 256>>>(r1w, r1b, r2w, r2b, r3w, r3b, (float*)d_out);
}